// round 13
// baseline (speedup 1.0000x reference)
#include <cuda_runtime.h>
#include <cuda_fp16.h>
#include <cstdint>
#include <cstddef>

#define BN_TOT 12800
#define RNN    512
#define EMB    300
#define EMBP   320
#define NGATE  2048
#define TSTEPS 8
#define K1     832     // 320 + 512
#define K2     1024    // 512 + 512

// ---------------- persistent device scratch ----------------
__device__ __half g_X[(size_t)TSTEPS * BN_TOT * EMBP];   // tanh(emb), fp16, padded
__device__ __half g_H1[2][(size_t)BN_TOT * RNN];
__device__ __half g_H2[2][(size_t)BN_TOT * RNN];
__device__ float  g_c1[(size_t)BN_TOT * RNN];
__device__ float  g_c2[(size_t)BN_TOT * RNN];
__device__ __half g_W1h[(size_t)NGATE * K1];   // row r = 4*n + gate (i,f,g,o), K-major
__device__ __half g_W2h[(size_t)NGATE * K2];
__device__ float  g_b1[NGATE];
__device__ float  g_b2[NGATE];

// ---------------- helpers ----------------
__device__ __forceinline__ uint32_t smem_u32(const void* p) {
    uint32_t a;
    asm("{ .reg .u64 t; cvta.to.shared.u64 t, %1; cvt.u32.u64 %0, t; }" : "=r"(a) : "l"(p));
    return a;
}
__device__ __forceinline__ void cp16(uint32_t dst, const void* src) {
    asm volatile("cp.async.cg.shared.global [%0], [%1], 16;\n" :: "r"(dst), "l"(src));
}
__device__ __forceinline__ void cp_commit() {
    asm volatile("cp.async.commit_group;\n" ::: "memory");
}
__device__ __forceinline__ void ldsm_x4(uint32_t* r, uint32_t addr) {
    asm volatile("ldmatrix.sync.aligned.m8n8.x4.shared.b16 {%0,%1,%2,%3}, [%4];"
                 : "=r"(r[0]), "=r"(r[1]), "=r"(r[2]), "=r"(r[3]) : "r"(addr));
}
__device__ __forceinline__ void mma16816(float* c, const uint32_t* a, uint32_t b0, uint32_t b1) {
    asm volatile(
        "mma.sync.aligned.m16n8k16.row.col.f32.f16.f16.f32 "
        "{%0,%1,%2,%3},{%4,%5,%6,%7},{%8,%9},{%0,%1,%2,%3};"
        : "+f"(c[0]), "+f"(c[1]), "+f"(c[2]), "+f"(c[3])
        : "r"(a[0]), "r"(a[1]), "r"(a[2]), "r"(a[3]), "r"(b0), "r"(b1));
}
__device__ __forceinline__ float tanh_fast(float x) {
    float y;
    asm("tanh.approx.f32 %0, %1;" : "=f"(y) : "f"(x));
    return y;
}
__device__ __forceinline__ float sigm_fast(float x) {
    return fmaf(tanh_fast(0.5f * x), 0.5f, 0.5f);
}
__device__ __forceinline__ uint32_t pack_h2(float a, float b) {
    __half2 t = __floats2half2_rn(a, b);
    return *(uint32_t*)&t;
}

#define STAGE_BYTES 32768
#define SMEM_BYTES  98304
#define GROW 68                 // epilogue gate-tile row stride in 4B words

// ---------------- pack / embed kernels ----------------
__global__ void pack_w1(const float* __restrict__ Wih, const float* __restrict__ Whh,
                        const float* __restrict__ bih, const float* __restrict__ bhh) {
    int idx = blockIdx.x * blockDim.x + threadIdx.x;
    if (idx >= NGATE * K1) return;
    int r = idx / K1, k = idx - r * K1;
    int src = (r & 3) * RNN + (r >> 2);
    float v = 0.f;
    if (k < EMB)        v = Wih[(size_t)src * EMB + k];
    else if (k >= EMBP) v = Whh[(size_t)src * RNN + (k - EMBP)];
    g_W1h[idx] = __float2half_rn(v);
    if (k == 0) g_b1[r] = bih[src] + bhh[src];
}
__global__ void pack_w2(const float* __restrict__ Wih, const float* __restrict__ Whh,
                        const float* __restrict__ bih, const float* __restrict__ bhh) {
    int idx = blockIdx.x * blockDim.x + threadIdx.x;
    if (idx >= NGATE * K2) return;
    int r = idx / K2, k = idx - r * K2;
    int src = (r & 3) * RNN + (r >> 2);
    float v = (k < RNN) ? Wih[(size_t)src * RNN + k] : Whh[(size_t)src * RNN + (k - RNN)];
    g_W2h[idx] = __float2half_rn(v);
    if (k == 0) g_b2[r] = bih[src] + bhh[src];
}
__global__ void embed_all(const int* __restrict__ sent, const float* __restrict__ w2v) {
    int idx = blockIdx.x * blockDim.x + threadIdx.x;       // < T*BN*160
    if (idx >= TSTEPS * BN_TOT * (EMBP / 2)) return;
    int row = idx / (EMBP / 2);
    int e   = (idx - row * (EMBP / 2)) * 2;
    int t = row / BN_TOT, bn = row - t * BN_TOT;
    int id = __ldg(&sent[bn * TSTEPS + t]);
    float v0 = 0.f, v1 = 0.f;
    if (e < EMB) {
        const float* w = &w2v[(size_t)id * EMB + e];
        v0 = tanhf(w[0]);          // exact: feeds both layers
        v1 = tanhf(w[1]);
    }
    ((__half2*)g_X)[idx] = __floats2half2_rn(v0, v1);
}

// ---------------- fused fp16 HMMA GEMM + LSTM cell (device core) ----------------
// Block tile 128x128x64. 8 warps 4(M)x2(N), warp tile 32x64. 3-stage cp.async,
// one barrier per chunk (issue at top, R11 shape), per-warp rotated ks order,
// fp16 gate staging in the epilogue.
template<int SPLIT, int KT, int S0, int WLD, int FIRST>
__device__ __forceinline__ void gemm_core(
    const __half* __restrict__ A0, const __half* __restrict__ A1,
    const __half* __restrict__ Wp, const float* __restrict__ bias,
    float* __restrict__ Cst, __half* __restrict__ Hd, float* __restrict__ out,
    int rowBase, int colBase, char* smem)
{
    const uint32_t sb = smem_u32(smem);
    const int tid = threadIdx.x, lane = tid & 31, warp = tid >> 5;
    const int wm = warp >> 1, wn = warp & 1;
    const int lrow = lane & 15, lhalf = lane >> 4;

    float acc[2][8][4];
    #pragma unroll
    for (int a = 0; a < 2; a++)
        #pragma unroll
        for (int b = 0; b < 8; b++)
            #pragma unroll
            for (int c = 0; c < 4; c++) acc[a][b][c] = 0.f;

    // --- hoisted cp.async addressing ---
    const int r0 = tid >> 3;                   // 0..31
    const int c0 = tid & 7;                    // 16B column
    const uint32_t d0 = (uint32_t)((r0 * 8 + (c0 ^ (r0 & 7))) << 4);   // +i*4096 rows r0+32i
    const __half* baseA0 = A0 + (size_t)(rowBase + r0) * S0  + c0 * 8;
    const __half* baseA1 = A1 + (size_t)(rowBase + r0) * RNN + c0 * 8;
    const __half* baseB  = Wp + (size_t)(colBase + r0) * WLD + c0 * 8;

    auto issue = [&](int chunk, int stg) {
        uint32_t base = sb + stg * STAGE_BYTES;
        if (chunk < SPLIT) {
            const __half* s = baseA0 + chunk * 64;
            #pragma unroll
            for (int i = 0; i < 4; i++) cp16(base + d0 + i * 4096, s + (size_t)(32 * i) * S0);
        } else {
            const __half* s = baseA1 + (chunk - SPLIT) * 64;
            #pragma unroll
            for (int i = 0; i < 4; i++) cp16(base + d0 + i * 4096, s + (size_t)(32 * i) * RNN);
        }
        const __half* sB = baseB + chunk * 64;
        #pragma unroll
        for (int i = 0; i < 4; i++) cp16(base + 16384 + d0 + i * 4096, sB + (size_t)(32 * i) * WLD);
        cp_commit();
    };

    // ldsm row offsets (per-thread constants); ks column xor computed inline
    uint32_t aoff[2], boff[4];
    #pragma unroll
    for (int mt = 0; mt < 2; mt++) aoff[mt] = (uint32_t)((wm * 32 + mt * 16 + lrow) * 128);
    #pragma unroll
    for (int nb = 0; nb < 4; nb++) boff[nb] = (uint32_t)(16384 + (wn * 64 + nb * 16 + lrow) * 128);
    const uint32_t xlo = (uint32_t)(lrow & 7);

    issue(0, 0);
    issue(1, 1);

    #pragma unroll 1
    for (int k = 0; k < KT; k++) {
        const int s = k % 3;
        if (k + 1 < KT) asm volatile("cp.async.wait_group 1;\n" ::: "memory");
        else            asm volatile("cp.async.wait_group 0;\n" ::: "memory");
        __syncthreads();                       // all warps done reading stage (k+2)%3 (iter k-1)
        if (k + 2 < KT) issue(k + 2, (k + 2) % 3);

        const uint32_t stBase = sb + s * STAGE_BYTES;
        #pragma unroll
        for (int ksi = 0; ksi < 4; ksi++) {
            const int ks = (ksi + warp) & 3;   // per-warp rotation (accum order-free)
            const uint32_t xk = ((((uint32_t)(ks << 1) + lhalf) ^ xlo) << 4);
            uint32_t afr[2][4];
            #pragma unroll
            for (int mt = 0; mt < 2; mt++) ldsm_x4(afr[mt], stBase + aoff[mt] + xk);
            uint32_t bfr[4][4];
            #pragma unroll
            for (int nb = 0; nb < 4; nb++) ldsm_x4(bfr[nb], stBase + boff[nb] + xk);
            #pragma unroll
            for (int mt = 0; mt < 2; mt++)
                #pragma unroll
                for (int nb = 0; nb < 4; nb++) {
                    mma16816(acc[mt][2 * nb],     afr[mt], bfr[nb][0], bfr[nb][2]);
                    mma16816(acc[mt][2 * nb + 1], afr[mt], bfr[nb][1], bfr[nb][3]);
                }
        }
    }
    __syncthreads();                           // before smem reuse as gate tile

    // ---- epilogue: acc -> fp16 gate tile in smem -> LSTM cell ----
    // slot 2h holds (i,f), slot 2h+1 holds (g,o); row stride GROW words.
    uint32_t* sG = (uint32_t*)smem;            // 128 x GROW
    #pragma unroll
    for (int mt = 0; mt < 2; mt++)
        #pragma unroll
        for (int nt = 0; nt < 8; nt++) {
            int r1 = wm * 32 + mt * 16 + (lane >> 2);
            int slot = wn * 32 + nt * 4 + (lane & 3);
            sG[r1 * GROW + slot]       = pack_h2(acc[mt][nt][0], acc[mt][nt][1]);
            sG[(r1 + 8) * GROW + slot] = pack_h2(acc[mt][nt][2], acc[mt][nt][3]);
        }
    __syncthreads();

    #pragma unroll
    for (int i = 0; i < 8; i++) {
        int p4 = tid + i * 256;                // 0..2047
        int ml = p4 >> 4;                      // row 0..127
        int q  = p4 & 15;                      // quad of slots -> 2 h values
        uint4 gw = *(const uint4*)&sG[ml * GROW + q * 4];
        __half2 w0 = *(__half2*)&gw.x;         // (i0,f0)
        __half2 w1 = *(__half2*)&gw.y;         // (g0,o0)
        __half2 w2 = *(__half2*)&gw.z;         // (i1,f1)
        __half2 w3 = *(__half2*)&gw.w;         // (g1,o1)
        float4 ba = *(const float4*)&bias[colBase + q * 8];
        float4 bb = *(const float4*)&bias[colBase + q * 8 + 4];
        int gm = rowBase + ml;
        int hb = (colBase >> 2) + q * 2;
        size_t cidx = (size_t)gm * RNN + hb;
        float2 cold = make_float2(0.f, 0.f);
        if (!FIRST) cold = *(const float2*)&Cst[cidx];
        float i0 = __low2float(w0) + ba.x, f0 = __high2float(w0) + ba.y;
        float g0 = __low2float(w1) + ba.z, o0 = __high2float(w1) + ba.w;
        float i1 = __low2float(w2) + bb.x, f1 = __high2float(w2) + bb.y;
        float g1 = __low2float(w3) + bb.z, o1 = __high2float(w3) + bb.w;
        float cn0 = sigm_fast(f0) * cold.x + sigm_fast(i0) * tanh_fast(g0);
        float cn1 = sigm_fast(f1) * cold.y + sigm_fast(i1) * tanh_fast(g1);
        float h0 = sigm_fast(o0) * tanh_fast(cn0);
        float h1 = sigm_fast(o1) * tanh_fast(cn1);
        *(float2*)&Cst[cidx] = make_float2(cn0, cn1);
        *(uint32_t*)&Hd[(size_t)gm * RNN + hb] = pack_h2(h0, h1);
        if (out) *(float2*)&out[cidx] = make_float2(h0, h1);
    }
}

// ---------------- global wrappers ----------------
__global__ void __launch_bounds__(256, 2) k_l1_first() {
    extern __shared__ char smem[];
    gemm_core<5, 5, EMBP, K1, 1>(g_X, g_H1[0], g_W1h, g_b1, g_c1, g_H1[1], nullptr,
                                 blockIdx.y * 128, blockIdx.x * 128, smem);
}
// Combined: layer2 step t  +  layer1 step t+1 (independent halves)
template<int FIRST2>
__global__ void __launch_bounds__(256, 2) k_step(int t) {
    extern __shared__ char smem[];
    const int p2 = t & 1, q2 = p2 ^ 1;
    if (blockIdx.y < 100) {
        gemm_core<8, (FIRST2 ? 8 : 16), RNN, K2, FIRST2>(
            g_H1[q2], g_H2[p2], g_W2h, g_b2, g_c2, g_H2[q2], nullptr,
            blockIdx.y * 128, blockIdx.x * 128, smem);
    } else {
        gemm_core<5, 13, EMBP, K1, 0>(
            g_X + (size_t)(t + 1) * BN_TOT * EMBP, g_H1[q2], g_W1h, g_b1, g_c1, g_H1[p2], nullptr,
            (blockIdx.y - 100) * 128, blockIdx.x * 128, smem);
    }
}
__global__ void __launch_bounds__(256, 2) k_l2_last(float* __restrict__ out) {
    extern __shared__ char smem[];
    gemm_core<8, 16, RNN, K2, 0>(g_H1[0], g_H2[1], g_W2h, g_b2, g_c2, g_H2[0], out,
                                 blockIdx.y * 128, blockIdx.x * 128, smem);
}

// ---------------- launch ----------------
extern "C" void kernel_launch(void* const* d_in, const int* in_sizes, int n_in,
                              void* d_out, int out_size) {
    (void)in_sizes; (void)n_in; (void)out_size;
    const int*   sentence = (const int*)d_in[0];
    const float* word2vec = (const float*)d_in[1];
    const float* W_ih1 = (const float*)d_in[2];
    const float* W_hh1 = (const float*)d_in[3];
    const float* b_ih1 = (const float*)d_in[4];
    const float* b_hh1 = (const float*)d_in[5];
    const float* W_ih2 = (const float*)d_in[6];
    const float* W_hh2 = (const float*)d_in[7];
    const float* b_ih2 = (const float*)d_in[8];
    const float* b_hh2 = (const float*)d_in[9];
    float* out = (float*)d_out;

    cudaFuncSetAttribute(k_l1_first, cudaFuncAttributeMaxDynamicSharedMemorySize, SMEM_BYTES);
    cudaFuncSetAttribute(k_step<1>,  cudaFuncAttributeMaxDynamicSharedMemorySize, SMEM_BYTES);
    cudaFuncSetAttribute(k_step<0>,  cudaFuncAttributeMaxDynamicSharedMemorySize, SMEM_BYTES);
    cudaFuncSetAttribute(k_l2_last,  cudaFuncAttributeMaxDynamicSharedMemorySize, SMEM_BYTES);

    pack_w1<<<(NGATE * K1 + 255) / 256, 256>>>(W_ih1, W_hh1, b_ih1, b_hh1);
    pack_w2<<<(NGATE * K2 + 255) / 256, 256>>>(W_ih2, W_hh2, b_ih2, b_hh2);
    embed_all<<<(TSTEPS * BN_TOT * (EMBP / 2) + 255) / 256, 256>>>(sentence, word2vec);

    dim3 g1(16, 100), gc(16, 200);
    k_l1_first<<<g1, 256, SMEM_BYTES>>>();
    k_step<1><<<gc, 256, SMEM_BYTES>>>(0);
    for (int t = 1; t < TSTEPS - 1; t++)
        k_step<0><<<gc, 256, SMEM_BYTES>>>(t);
    k_l2_last<<<g1, 256, SMEM_BYTES>>>(out);
}

// round 14
// speedup vs baseline: 1.4449x; 1.4449x over previous
#include <cuda_runtime.h>
#include <cuda_fp16.h>
#include <cstdint>
#include <cstddef>

#define BN_TOT 12800
#define RNN    512
#define EMB    300
#define EMBP   320
#define NGATE  2048
#define TSTEPS 8
#define K1     832     // 320 + 512
#define K2     1024    // 512 + 512

// ---------------- persistent device scratch ----------------
__device__ __half g_X[(size_t)TSTEPS * BN_TOT * EMBP];   // tanh(emb), fp16, padded
__device__ __half g_H1[2][(size_t)BN_TOT * RNN];
__device__ __half g_H2[2][(size_t)BN_TOT * RNN];
__device__ float  g_c1[(size_t)BN_TOT * RNN];
__device__ float  g_c2[(size_t)BN_TOT * RNN];
__device__ __half g_W1h[(size_t)NGATE * K1];   // row r = 4*n + gate (i,f,g,o), K-major
__device__ __half g_W2h[(size_t)NGATE * K2];
__device__ float  g_b1[NGATE];
__device__ float  g_b2[NGATE];

// ---------------- helpers ----------------
__device__ __forceinline__ uint32_t smem_u32(const void* p) {
    uint32_t a;
    asm("{ .reg .u64 t; cvta.to.shared.u64 t, %1; cvt.u32.u64 %0, t; }" : "=r"(a) : "l"(p));
    return a;
}
__device__ __forceinline__ void cp16(uint32_t dst, const void* src) {
    asm volatile("cp.async.cg.shared.global [%0], [%1], 16;\n" :: "r"(dst), "l"(src));
}
__device__ __forceinline__ void cp_commit() {
    asm volatile("cp.async.commit_group;\n" ::: "memory");
}
__device__ __forceinline__ void ldsm_x4(uint32_t* r, uint32_t addr) {
    asm volatile("ldmatrix.sync.aligned.m8n8.x4.shared.b16 {%0,%1,%2,%3}, [%4];"
                 : "=r"(r[0]), "=r"(r[1]), "=r"(r[2]), "=r"(r[3]) : "r"(addr));
}
__device__ __forceinline__ void mma16816(float* c, const uint32_t* a, uint32_t b0, uint32_t b1) {
    asm volatile(
        "mma.sync.aligned.m16n8k16.row.col.f32.f16.f16.f32 "
        "{%0,%1,%2,%3},{%4,%5,%6,%7},{%8,%9},{%0,%1,%2,%3};"
        : "+f"(c[0]), "+f"(c[1]), "+f"(c[2]), "+f"(c[3])
        : "r"(a[0]), "r"(a[1]), "r"(a[2]), "r"(a[3]), "r"(b0), "r"(b1));
}
__device__ __forceinline__ float tanh_fast(float x) {
    float y;
    asm("tanh.approx.f32 %0, %1;" : "=f"(y) : "f"(x));
    return y;
}
__device__ __forceinline__ float sigm_fast(float x) {
    return fmaf(tanh_fast(0.5f * x), 0.5f, 0.5f);
}

#define STAGE_BYTES 32768
#define SMEM_BYTES  98304

// ---------------- pack / embed kernels ----------------
// half2 stores; K1/2=416 pairs per row, pairs never straddle region boundaries badly
__global__ void pack_w1(const float* __restrict__ Wih, const float* __restrict__ Whh,
                        const float* __restrict__ bih, const float* __restrict__ bhh) {
    int idx = blockIdx.x * blockDim.x + threadIdx.x;
    if (idx >= NGATE * (K1 / 2)) return;
    int r = idx / (K1 / 2), k = (idx - r * (K1 / 2)) * 2;
    int src = (r & 3) * RNN + (r >> 2);
    float v0 = 0.f, v1 = 0.f;
    if (k < EMB) {
        v0 = Wih[(size_t)src * EMB + k];
        if (k + 1 < EMB) v1 = Wih[(size_t)src * EMB + k + 1];
    } else if (k >= EMBP) {
        v0 = Whh[(size_t)src * RNN + (k - EMBP)];
        v1 = Whh[(size_t)src * RNN + (k + 1 - EMBP)];
    }
    ((__half2*)g_W1h)[idx] = __floats2half2_rn(v0, v1);
    if (k == 0) g_b1[r] = bih[src] + bhh[src];
}
__global__ void pack_w2(const float* __restrict__ Wih, const float* __restrict__ Whh,
                        const float* __restrict__ bih, const float* __restrict__ bhh) {
    int idx = blockIdx.x * blockDim.x + threadIdx.x;
    if (idx >= NGATE * (K2 / 2)) return;
    int r = idx / (K2 / 2), k = (idx - r * (K2 / 2)) * 2;
    int src = (r & 3) * RNN + (r >> 2);
    float v0, v1;
    if (k < RNN) { v0 = Wih[(size_t)src * RNN + k];       v1 = Wih[(size_t)src * RNN + k + 1]; }
    else         { v0 = Whh[(size_t)src * RNN + (k - RNN)]; v1 = Whh[(size_t)src * RNN + (k + 1 - RNN)]; }
    ((__half2*)g_W2h)[idx] = __floats2half2_rn(v0, v1);
    if (k == 0) g_b2[r] = bih[src] + bhh[src];
}
__global__ void embed_all(const int* __restrict__ sent, const float* __restrict__ w2v) {
    int idx = blockIdx.x * blockDim.x + threadIdx.x;       // < T*BN*160
    if (idx >= TSTEPS * BN_TOT * (EMBP / 2)) return;
    int row = idx / (EMBP / 2);
    int e   = (idx - row * (EMBP / 2)) * 2;
    int t = row / BN_TOT, bn = row - t * BN_TOT;
    int id = __ldg(&sent[bn * TSTEPS + t]);
    float v0 = 0.f, v1 = 0.f;
    if (e < EMB) {
        const float* w = &w2v[(size_t)id * EMB + e];
        v0 = tanh_fast(w[0]);
        v1 = tanh_fast(w[1]);
    }
    ((__half2*)g_X)[idx] = __floats2half2_rn(v0, v1);
}

// ---------------- fused fp16 HMMA GEMM + LSTM cell (device core) ----------------
// Block tile 128x128x64. 8 warps 4(M)x2(N), warp tile 32x64. 3-stage cp.async,
// one barrier per chunk, per-warp rotated ks order. (R11 winner shape.)
template<int SPLIT, int KT, int S0, int WLD, int FIRST>
__device__ __forceinline__ void gemm_core(
    const __half* __restrict__ A0, const __half* __restrict__ A1,
    const __half* __restrict__ Wp, const float* __restrict__ bias,
    float* __restrict__ Cst, __half* __restrict__ Hd, float* __restrict__ out,
    int rowBase, int colBase, char* smem)
{
    const uint32_t sb = smem_u32(smem);
    const int tid = threadIdx.x, lane = tid & 31, warp = tid >> 5;
    const int wm = warp >> 1, wn = warp & 1;
    const int lrow = lane & 15, lhalf = lane >> 4;

    float acc[2][8][4];
    #pragma unroll
    for (int a = 0; a < 2; a++)
        #pragma unroll
        for (int b = 0; b < 8; b++)
            #pragma unroll
            for (int c = 0; c < 4; c++) acc[a][b][c] = 0.f;

    // --- hoisted cp.async addressing ---
    const int r0 = tid >> 3;                   // 0..31
    const int c0 = tid & 7;                    // 16B column
    const uint32_t d0 = (uint32_t)((r0 * 8 + (c0 ^ (r0 & 7))) << 4);   // +i*4096 rows r0+32i
    const __half* baseA0 = A0 + (size_t)(rowBase + r0) * S0  + c0 * 8;
    const __half* baseA1 = A1 + (size_t)(rowBase + r0) * RNN + c0 * 8;
    const __half* baseB  = Wp + (size_t)(colBase + r0) * WLD + c0 * 8;

    auto issue = [&](int chunk, int stg) {
        uint32_t base = sb + stg * STAGE_BYTES;
        if (chunk < SPLIT) {
            const __half* s = baseA0 + chunk * 64;
            #pragma unroll
            for (int i = 0; i < 4; i++) cp16(base + d0 + i * 4096, s + (size_t)(32 * i) * S0);
        } else {
            const __half* s = baseA1 + (chunk - SPLIT) * 64;
            #pragma unroll
            for (int i = 0; i < 4; i++) cp16(base + d0 + i * 4096, s + (size_t)(32 * i) * RNN);
        }
        const __half* sB = baseB + chunk * 64;
        #pragma unroll
        for (int i = 0; i < 4; i++) cp16(base + 16384 + d0 + i * 4096, sB + (size_t)(32 * i) * WLD);
        cp_commit();
    };

    // ldsm row offsets (per-thread constants); ks column xor computed inline
    uint32_t aoff[2], boff[4];
    #pragma unroll
    for (int mt = 0; mt < 2; mt++) aoff[mt] = (uint32_t)((wm * 32 + mt * 16 + lrow) * 128);
    #pragma unroll
    for (int nb = 0; nb < 4; nb++) boff[nb] = (uint32_t)(16384 + (wn * 64 + nb * 16 + lrow) * 128);
    const uint32_t xlo = (uint32_t)(lrow & 7);

    issue(0, 0);
    issue(1, 1);

    #pragma unroll 1
    for (int k = 0; k < KT; k++) {
        const int s = k % 3;
        if (k + 1 < KT) asm volatile("cp.async.wait_group 1;\n" ::: "memory");
        else            asm volatile("cp.async.wait_group 0;\n" ::: "memory");
        __syncthreads();                       // all warps done reading stage (k+2)%3 (iter k-1)
        if (k + 2 < KT) issue(k + 2, (k + 2) % 3);

        const uint32_t stBase = sb + s * STAGE_BYTES;
        #pragma unroll
        for (int ksi = 0; ksi < 4; ksi++) {
            const int ks = (ksi + warp) & 3;   // per-warp rotation (accum order-free)
            const uint32_t xk = ((((uint32_t)(ks << 1) + lhalf) ^ xlo) << 4);
            uint32_t afr[2][4];
            #pragma unroll
            for (int mt = 0; mt < 2; mt++) ldsm_x4(afr[mt], stBase + aoff[mt] + xk);
            uint32_t bfr[4][4];
            #pragma unroll
            for (int nb = 0; nb < 4; nb++) ldsm_x4(bfr[nb], stBase + boff[nb] + xk);
            #pragma unroll
            for (int mt = 0; mt < 2; mt++)
                #pragma unroll
                for (int nb = 0; nb < 4; nb++) {
                    mma16816(acc[mt][2 * nb],     afr[mt], bfr[nb][0], bfr[nb][2]);
                    mma16816(acc[mt][2 * nb + 1], afr[mt], bfr[nb][1], bfr[nb][3]);
                }
        }
    }
    __syncthreads();                           // before smem reuse as epilogue tile

    // ---- epilogue: acc -> fp32 smem gate tile -> LSTM cell (R11 shape) ----
    float* sC = (float*)smem;                  // 128 x 132
    #pragma unroll
    for (int mt = 0; mt < 2; mt++)
        #pragma unroll
        for (int nt = 0; nt < 8; nt++) {
            int r = wm * 32 + mt * 16 + (lane >> 2);
            int c = wn * 64 + nt * 8 + ((lane & 3) << 1);
            sC[r * 132 + c]           = acc[mt][nt][0];
            sC[r * 132 + c + 1]       = acc[mt][nt][1];
            sC[(r + 8) * 132 + c]     = acc[mt][nt][2];
            sC[(r + 8) * 132 + c + 1] = acc[mt][nt][3];
        }
    __syncthreads();

    #pragma unroll
    for (int i = 0; i < 4; i++) {
        int p4 = tid + i * 256;                // 0..1023
        int ml = p4 >> 3;                      // row 0..127
        int hg = p4 & 7;                       // group of 4 h cols
        const float* sp = &sC[ml * 132 + hg * 16];
        int gm = rowBase + ml;
        int gh = (colBase >> 2) + hg * 4;
        size_t cidx = (size_t)gm * RNN + gh;
        float4 cold = make_float4(0.f, 0.f, 0.f, 0.f);
        if (!FIRST) cold = *(const float4*)&Cst[cidx];
        float cn[4], hv[4];
        #pragma unroll
        for (int j = 0; j < 4; j++) {
            float4 gq = *(const float4*)&sp[j * 4];
            float4 bq = *(const float4*)&bias[colBase + hg * 16 + j * 4];
            float gi = gq.x + bq.x;
            float gf = gq.y + bq.y;
            float gg = gq.z + bq.z;
            float go = gq.w + bq.w;
            float co = (&cold.x)[j];
            cn[j] = sigm_fast(gf) * co + sigm_fast(gi) * tanh_fast(gg);
            hv[j] = sigm_fast(go) * tanh_fast(cn[j]);
        }
        *(float4*)&Cst[cidx] = make_float4(cn[0], cn[1], cn[2], cn[3]);
        if (Hd) {
            __half hh[4];
            #pragma unroll
            for (int j = 0; j < 4; j++) hh[j] = __float2half_rn(hv[j]);
            *(uint2*)&Hd[(size_t)gm * RNN + gh] = *(uint2*)hh;
        }
        if (out) *(float4*)&out[cidx] = make_float4(hv[0], hv[1], hv[2], hv[3]);
    }
}

// ---------------- global wrappers ----------------
__global__ void __launch_bounds__(256, 2) k_l1_first() {
    extern __shared__ char smem[];
    gemm_core<5, 5, EMBP, K1, 1>(g_X, g_H1[0], g_W1h, g_b1, g_c1, g_H1[1], nullptr,
                                 blockIdx.y * 128, blockIdx.x * 128, smem);
}
// Combined: layer2 step t  +  layer1 step t+1 (independent halves)
template<int FIRST2>
__global__ void __launch_bounds__(256, 2) k_step(int t) {
    extern __shared__ char smem[];
    const int p2 = t & 1, q2 = p2 ^ 1;
    if (blockIdx.y < 100) {
        gemm_core<8, (FIRST2 ? 8 : 16), RNN, K2, FIRST2>(
            g_H1[q2], g_H2[p2], g_W2h, g_b2, g_c2, g_H2[q2], nullptr,
            blockIdx.y * 128, blockIdx.x * 128, smem);
    } else {
        gemm_core<5, 13, EMBP, K1, 0>(
            g_X + (size_t)(t + 1) * BN_TOT * EMBP, g_H1[q2], g_W1h, g_b1, g_c1, g_H1[p2], nullptr,
            (blockIdx.y - 100) * 128, blockIdx.x * 128, smem);
    }
}
// Final layer2 step 7: writes out only (h2 no longer needed by anyone)
__global__ void __launch_bounds__(256, 2) k_l2_last(float* __restrict__ out) {
    extern __shared__ char smem[];
    gemm_core<8, 16, RNN, K2, 0>(g_H1[0], g_H2[1], g_W2h, g_b2, g_c2, nullptr, out,
                                 blockIdx.y * 128, blockIdx.x * 128, smem);
}

// ---------------- launch ----------------
extern "C" void kernel_launch(void* const* d_in, const int* in_sizes, int n_in,
                              void* d_out, int out_size) {
    (void)in_sizes; (void)n_in; (void)out_size;
    const int*   sentence = (const int*)d_in[0];
    const float* word2vec = (const float*)d_in[1];
    const float* W_ih1 = (const float*)d_in[2];
    const float* W_hh1 = (const float*)d_in[3];
    const float* b_ih1 = (const float*)d_in[4];
    const float* b_hh1 = (const float*)d_in[5];
    const float* W_ih2 = (const float*)d_in[6];
    const float* W_hh2 = (const float*)d_in[7];
    const float* b_ih2 = (const float*)d_in[8];
    const float* b_hh2 = (const float*)d_in[9];
    float* out = (float*)d_out;

    cudaFuncSetAttribute(k_l1_first, cudaFuncAttributeMaxDynamicSharedMemorySize, SMEM_BYTES);
    cudaFuncSetAttribute(k_step<1>,  cudaFuncAttributeMaxDynamicSharedMemorySize, SMEM_BYTES);
    cudaFuncSetAttribute(k_step<0>,  cudaFuncAttributeMaxDynamicSharedMemorySize, SMEM_BYTES);
    cudaFuncSetAttribute(k_l2_last,  cudaFuncAttributeMaxDynamicSharedMemorySize, SMEM_BYTES);

    pack_w1<<<(NGATE * (K1 / 2) + 255) / 256, 256>>>(W_ih1, W_hh1, b_ih1, b_hh1);
    pack_w2<<<(NGATE * (K2 / 2) + 255) / 256, 256>>>(W_ih2, W_hh2, b_ih2, b_hh2);
    embed_all<<<(TSTEPS * BN_TOT * (EMBP / 2) + 255) / 256, 256>>>(sentence, word2vec);

    dim3 g1(16, 100), gc(16, 200);
    k_l1_first<<<g1, 256, SMEM_BYTES>>>();
    k_step<1><<<gc, 256, SMEM_BYTES>>>(0);
    for (int t = 1; t < TSTEPS - 1; t++)
        k_step<0><<<gc, 256, SMEM_BYTES>>>(t);
    k_l2_last<<<g1, 256, SMEM_BYTES>>>(out);
}